// round 13
// baseline (speedup 1.0000x reference)
#include <cuda_runtime.h>
#include <cuda_bf16.h>

// ChamferLoss via exact uniform-grid nearest neighbor (G=32).
// pred[32768,3], target[32768,3] float32, out = mean NN^2 both directions.
//
// 1. histogram  2. scan stage1 (per-tile, self-zeroes counts for next replay)
// 3. scan stage2 (per-block prefix of tile sums, writes CSR starts)
// 4. scatter (cell-sorted, carries original index)
// 5. query: TWO LANES PER QUERY (parity row split, pairwise shfl-min combine),
//    center-row-first + slab-distance row pruning, exact termination
// 6. single-kernel deterministic reduction.

#define NPTS   32768
#define NALL   65536
#define G      32
#define NC     (G*G*G)       // 32768 cells per set
#define NC2    (2*NC)        // 65536
#define GLO    (-4.0f)
#define GH     (0.25f)       // 8/32, exact
#define GINV   (4.0f)        // 1/GH, exact
#define FINF   3.4e38f

__device__ uint    g_cnt[NC2];       // zero at start of every run (see k_scan1)
__device__ uint    g_scanpart[NC2];
__device__ uint    g_bsum[64];
__device__ uint    g_start[NC2 + 1];
__device__ uint    g_cursor[NC2];
__device__ float4  g_pts[NALL];      // cell-sorted; .w = original global idx bits
__device__ float   g_minv[NALL];     // per-ORIGINAL-index min sq distance

__device__ __forceinline__ int cellof(float v) {
    int c = (int)floorf((v - GLO) * GINV);
    return min(max(c, 0), G - 1);
}
// distance from q to the slab of cell index c along one axis (0 if inside)
__device__ __forceinline__ float slabdist(float q, int c) {
    float l = GLO + c * GH;
    return fmaxf(0.0f, fmaxf(l - q, q - (l + GH)));
}

// ---------------- 1. histogram (g_cnt is zero on entry, every run) --------
__global__ void __launch_bounds__(256) k_hist(const float* __restrict__ pred,
                                              const float* __restrict__ target) {
    int i = blockIdx.x * 256 + threadIdx.x;          // 0..NALL-1
    int s = i >> 15;
    int li = i & (NPTS - 1);
    const float* src = s ? target : pred;
    float x = src[3 * li], y = src[3 * li + 1], z = src[3 * li + 2];
    int c = ((cellof(z) * G + cellof(y)) * G + cellof(x)) + s * NC;
    atomicAdd(&g_cnt[c], 1u);
}

// ------ 2. scan stage 1: per-1024-cell tile; re-zeroes g_cnt after read ----
__global__ void __launch_bounds__(256) k_scan1() {
    __shared__ uint sm[256];
    int t = threadIdx.x;
    int base = blockIdx.x * 1024 + t * 4;
    uint4 c4 = *(const uint4*)&g_cnt[base];
    *(uint4*)&g_cnt[base] = make_uint4(0, 0, 0, 0);   // clean for next replay
    uint s = c4.x + c4.y + c4.z + c4.w;
    sm[t] = s; __syncthreads();
    for (int off = 1; off < 256; off <<= 1) {
        uint v = (t >= off) ? sm[t - off] : 0u;
        __syncthreads();
        sm[t] += v;
        __syncthreads();
    }
    uint excl = sm[t] - s;
    g_scanpart[base]     = excl;
    g_scanpart[base + 1] = excl + c4.x;
    g_scanpart[base + 2] = excl + c4.x + c4.y;
    g_scanpart[base + 3] = excl + c4.x + c4.y + c4.z;
    if (t == 255) g_bsum[blockIdx.x] = sm[255];
}

// ------ 3. scan stage 2: each block derives its own tile prefix, applies ---
__global__ void __launch_bounds__(256) k_scan2apply() {
    __shared__ uint soff;
    int t = threadIdx.x;
    if (t < 32) {
        uint a = (2 * t     < (int)blockIdx.x) ? g_bsum[2 * t]     : 0u;
        uint b = (2 * t + 1 < (int)blockIdx.x) ? g_bsum[2 * t + 1] : 0u;
        uint v = a + b;
#pragma unroll
        for (int o = 16; o > 0; o >>= 1)
            v += __shfl_down_sync(0xFFFFFFFFu, v, o);
        if (t == 0) soff = v;
    }
    __syncthreads();
    uint off = soff;
    int base = blockIdx.x * 1024 + t * 4;
#pragma unroll
    for (int k = 0; k < 4; k++) {
        uint v = g_scanpart[base + k] + off;
        g_start[base + k] = v;
        g_cursor[base + k] = v;
    }
    if (blockIdx.x == 63 && t == 255) g_start[NC2] = NALL;
}

// ---------------- 4. scatter (sorted by cell) ----------------
__global__ void __launch_bounds__(256) k_scatter(const float* __restrict__ pred,
                                                 const float* __restrict__ target) {
    int i = blockIdx.x * 256 + threadIdx.x;          // global original idx
    int s = i >> 15;
    int li = i & (NPTS - 1);
    const float* src = s ? target : pred;
    float x = src[3 * li], y = src[3 * li + 1], z = src[3 * li + 2];
    int c = ((cellof(z) * G + cellof(y)) * G + cellof(x)) + s * NC;
    uint pos = atomicAdd(&g_cursor[c], 1u);
    g_pts[pos] = make_float4(x, y, z, __int_as_float(i));
}

// ---------------- 5. query: 2 lanes/query pruned expanding-box exact NN ----
__device__ __forceinline__ void scan_range(uint k0, uint k1,
                                           float qx, float qy, float qz,
                                           float& best) {
    for (uint k = k0; k < k1; k++) {
        float4 p = g_pts[k];
        float dx = p.x - qx, dy = p.y - qy, dz = p.z - qz;
        best = fminf(best, fmaf(dx, dx, fmaf(dy, dy, dz * dz)));
    }
}

__global__ void __launch_bounds__(256) k_query2() {
    int gt = blockIdx.x * 256 + threadIdx.x;         // 0 .. 2*NALL-1
    int i  = gt >> 1;                                // sorted query position
    int h  = gt & 1;                                 // half: 0 or 1
    uint pmask = 0x3u << (threadIdx.x & 30u);        // the two lanes of this pair

    float4 q = g_pts[i];
    int s = i >> 15;                                 // set of this query
    int tb = (s ^ 1) * NC;                           // target grid base
    float qx = q.x, qy = q.y, qz = q.z;
    int cx = cellof(qx), cy = cellof(qy), cz = cellof(qz);

    // distance of the query outside its (clamped) cell: keeps bound exact
    float ex = fmaxf(slabdist(qx, cx), fmaxf(slabdist(qy, cy), slabdist(qz, cz)));

    float best = FINF;

    // ---- r = 1: BOTH lanes scan the center row (tight prune bound), then
    //      the remaining 8 rows split by parity ----
    {
        int x0 = max(cx - 1, 0), x1 = min(cx + 1, G - 1);
        int rbc = (cz * G + cy) * G + tb;
        scan_range(g_start[rbc + x0], g_start[rbc + x1 + 1], qx, qy, qz, best);

        int z0 = max(cz - 1, 0), z1 = min(cz + 1, G - 1);
        int y0 = max(cy - 1, 0), y1 = min(cy + 1, G - 1);
        int c = 0;
        for (int z = z0; z <= z1; z++) {
            float dzs = slabdist(qz, z);
            float dz2 = dzs * dzs;
            for (int y = y0; y <= y1; y++) {
                if (z == cz && y == cy) continue;
                if ((c++ & 1) != h) continue;          // my half of the rows
                float dys = slabdist(qy, y);
                if (fmaf(dys, dys, dz2) >= best) continue;
                int rb = (z * G + y) * G + tb;
                scan_range(g_start[rb + x0], g_start[rb + x1 + 1], qx, qy, qz, best);
            }
        }
        best = fminf(best, __shfl_xor_sync(pmask, best, 1));  // pair combine
    }

    // ---- escalation: pruned box per radius, rows split by parity ----
    int r = 1;
    for (;;) {
        float bnd = (float)r * GH - ex;   // unexamined cells are farther than this
        if ((bnd > 0.0f && best <= bnd * bnd) || r >= G) break;
        r++;
        int z0 = max(cz - r, 0), z1 = min(cz + r, G - 1);
        int y0 = max(cy - r, 0), y1 = min(cy + r, G - 1);
        int x0 = max(cx - r, 0), x1 = min(cx + r, G - 1);
        int c = 0;
        for (int z = z0; z <= z1; z++) {
            float dzs = slabdist(qz, z);
            float dz2 = dzs * dzs;
            for (int y = y0; y <= y1; y++) {
                if ((c++ & 1) != h) continue;
                float dys = slabdist(qy, y);
                if (fmaf(dys, dys, dz2) >= best) continue;
                int rb = (z * G + y) * G + tb;
                scan_range(g_start[rb + x0], g_start[rb + x1 + 1], qx, qy, qz, best);
            }
        }
        best = fminf(best, __shfl_xor_sync(pmask, best, 1));  // sync pair state
    }

    if (h == 0)
        g_minv[__float_as_int(q.w)] = best;   // by ORIGINAL index: deterministic
}

// ---------------- 6. single-kernel deterministic reduction ----------------
__global__ void __launch_bounds__(1024) k_reduce(float* __restrict__ out) {
    __shared__ float sm[1024];
    int t = threadIdx.x;
    float acc = 0.0f;
    const float4* mv = (const float4*)g_minv;
#pragma unroll
    for (int k = 0; k < NALL / 4096; k++) {          // 16 x float4 per thread
        float4 v = mv[t + k * 1024];
        acc += (v.x + v.y) + (v.z + v.w);
    }
    sm[t] = acc; __syncthreads();
    for (int stride = 512; stride > 0; stride >>= 1) {
        if (t < stride) sm[t] += sm[t + stride];
        __syncthreads();
    }
    if (t == 0) out[0] = sm[0] / (float)NPTS;
}

extern "C" void kernel_launch(void* const* d_in, const int* in_sizes, int n_in,
                              void* d_out, int out_size) {
    const float* pred   = (const float*)d_in[0];
    const float* target = (const float*)d_in[1];
    float* out = (float*)d_out;

    k_hist      <<<NALL / 256, 256>>>(pred, target);
    k_scan1     <<<NC2 / 1024, 256>>>();
    k_scan2apply<<<NC2 / 1024, 256>>>();
    k_scatter   <<<NALL / 256, 256>>>(pred, target);
    k_query2    <<<2 * NALL / 256, 256>>>();
    k_reduce    <<<1, 1024>>>(out);
}

// round 14
// speedup vs baseline: 1.2034x; 1.2034x over previous
#include <cuda_runtime.h>
#include <cuda_bf16.h>

// ChamferLoss via exact uniform-grid nearest neighbor (G=32).
// pred[32768,3], target[32768,3] float32, out = mean NN^2 both directions.
//
// 1. histogram  2. scan stage1 (per-tile, self-zeroes counts for next replay)
// 3. scan stage2 (per-block prefix of tile sums, writes CSR starts)
// 4. scatter (cell-sorted, carries original index)
// 5. query: one thread/query, center-row-first + slab-distance row pruning
//    (exact R8/76.2us form)
// 6. single-kernel deterministic reduction (float4 loads).

#define NPTS   32768
#define NALL   65536
#define G      32
#define NC     (G*G*G)       // 32768 cells per set
#define NC2    (2*NC)        // 65536
#define GLO    (-4.0f)
#define GH     (0.25f)       // 8/32, exact
#define GINV   (4.0f)        // 1/GH, exact
#define FINF   3.4e38f

__device__ uint    g_cnt[NC2];       // zero at start of every run (see k_scan1)
__device__ uint    g_scanpart[NC2];
__device__ uint    g_bsum[64];
__device__ uint    g_start[NC2 + 1];
__device__ uint    g_cursor[NC2];
__device__ float4  g_pts[NALL];      // cell-sorted; .w = original global idx bits
__device__ float   g_minv[NALL];     // per-ORIGINAL-index min sq distance

__device__ __forceinline__ int cellof(float v) {
    int c = (int)floorf((v - GLO) * GINV);
    return min(max(c, 0), G - 1);
}
// distance from q to the slab of cell index c along one axis (0 if inside)
__device__ __forceinline__ float slabdist(float q, int c) {
    float l = GLO + c * GH;
    return fmaxf(0.0f, fmaxf(l - q, q - (l + GH)));
}

// ---------------- 1. histogram (g_cnt is zero on entry, every run) --------
__global__ void __launch_bounds__(256) k_hist(const float* __restrict__ pred,
                                              const float* __restrict__ target) {
    int i = blockIdx.x * 256 + threadIdx.x;          // 0..NALL-1
    int s = i >> 15;
    int li = i & (NPTS - 1);
    const float* src = s ? target : pred;
    float x = src[3 * li], y = src[3 * li + 1], z = src[3 * li + 2];
    int c = ((cellof(z) * G + cellof(y)) * G + cellof(x)) + s * NC;
    atomicAdd(&g_cnt[c], 1u);
}

// ------ 2. scan stage 1: per-1024-cell tile; re-zeroes g_cnt after read ----
__global__ void __launch_bounds__(256) k_scan1() {
    __shared__ uint sm[256];
    int t = threadIdx.x;
    int base = blockIdx.x * 1024 + t * 4;
    uint4 c4 = *(const uint4*)&g_cnt[base];
    *(uint4*)&g_cnt[base] = make_uint4(0, 0, 0, 0);   // clean for next replay
    uint s = c4.x + c4.y + c4.z + c4.w;
    sm[t] = s; __syncthreads();
    for (int off = 1; off < 256; off <<= 1) {
        uint v = (t >= off) ? sm[t - off] : 0u;
        __syncthreads();
        sm[t] += v;
        __syncthreads();
    }
    uint excl = sm[t] - s;
    g_scanpart[base]     = excl;
    g_scanpart[base + 1] = excl + c4.x;
    g_scanpart[base + 2] = excl + c4.x + c4.y;
    g_scanpart[base + 3] = excl + c4.x + c4.y + c4.z;
    if (t == 255) g_bsum[blockIdx.x] = sm[255];
}

// ------ 3. scan stage 2: each block derives its own tile prefix, applies ---
__global__ void __launch_bounds__(256) k_scan2apply() {
    __shared__ uint soff;
    int t = threadIdx.x;
    if (t < 32) {
        uint a = (2 * t     < (int)blockIdx.x) ? g_bsum[2 * t]     : 0u;
        uint b = (2 * t + 1 < (int)blockIdx.x) ? g_bsum[2 * t + 1] : 0u;
        uint v = a + b;
#pragma unroll
        for (int o = 16; o > 0; o >>= 1)
            v += __shfl_down_sync(0xFFFFFFFFu, v, o);
        if (t == 0) soff = v;
    }
    __syncthreads();
    uint off = soff;
    int base = blockIdx.x * 1024 + t * 4;
#pragma unroll
    for (int k = 0; k < 4; k++) {
        uint v = g_scanpart[base + k] + off;
        g_start[base + k] = v;
        g_cursor[base + k] = v;
    }
    if (blockIdx.x == 63 && t == 255) g_start[NC2] = NALL;
}

// ---------------- 4. scatter (sorted by cell) ----------------
__global__ void __launch_bounds__(256) k_scatter(const float* __restrict__ pred,
                                                 const float* __restrict__ target) {
    int i = blockIdx.x * 256 + threadIdx.x;          // global original idx
    int s = i >> 15;
    int li = i & (NPTS - 1);
    const float* src = s ? target : pred;
    float x = src[3 * li], y = src[3 * li + 1], z = src[3 * li + 2];
    int c = ((cellof(z) * G + cellof(y)) * G + cellof(x)) + s * NC;
    uint pos = atomicAdd(&g_cursor[c], 1u);
    g_pts[pos] = make_float4(x, y, z, __int_as_float(i));
}

// ---------------- 5. query: pruned expanding-box exact NN ----------------
__device__ __forceinline__ void scan_range(uint k0, uint k1,
                                           float qx, float qy, float qz,
                                           float& best) {
    for (uint k = k0; k < k1; k++) {
        float4 p = g_pts[k];
        float dx = p.x - qx, dy = p.y - qy, dz = p.z - qz;
        best = fminf(best, fmaf(dx, dx, fmaf(dy, dy, dz * dz)));
    }
}

__global__ void __launch_bounds__(256) k_query() {
    int i = blockIdx.x * 256 + threadIdx.x;          // sorted position
    float4 q = g_pts[i];
    int s = i >> 15;                                 // set of this query
    int tb = (s ^ 1) * NC;                           // target grid base
    float qx = q.x, qy = q.y, qz = q.z;
    int cx = cellof(qx), cy = cellof(qy), cz = cellof(qz);

    // distance of the query outside its (clamped) cell: keeps bound exact
    float ex = fmaxf(slabdist(qx, cx), fmaxf(slabdist(qy, cy), slabdist(qz, cz)));

    float best = FINF;

    // ---- r = 1: center row first (tight best), then pruned rows ----
    {
        int x0 = max(cx - 1, 0), x1 = min(cx + 1, G - 1);
        int rbc = (cz * G + cy) * G + tb;
        scan_range(g_start[rbc + x0], g_start[rbc + x1 + 1], qx, qy, qz, best);

        int z0 = max(cz - 1, 0), z1 = min(cz + 1, G - 1);
        int y0 = max(cy - 1, 0), y1 = min(cy + 1, G - 1);
        for (int z = z0; z <= z1; z++) {
            float dz = slabdist(qz, z);
            float dz2 = dz * dz;
            for (int y = y0; y <= y1; y++) {
                if (z == cz && y == cy) continue;
                float dy = slabdist(qy, y);
                if (fmaf(dy, dy, dz2) >= best) continue;   // row cannot improve
                int rb = (z * G + y) * G + tb;
                scan_range(g_start[rb + x0], g_start[rb + x1 + 1], qx, qy, qz, best);
            }
        }
    }

    // ---- escalation: full pruned box per radius, exact termination ----
    int r = 1;
    for (;;) {
        float bnd = (float)r * GH - ex;   // unexamined cells are farther than this
        if ((bnd > 0.0f && best <= bnd * bnd) || r >= G) break;
        r++;
        int z0 = max(cz - r, 0), z1 = min(cz + r, G - 1);
        int y0 = max(cy - r, 0), y1 = min(cy + r, G - 1);
        int x0 = max(cx - r, 0), x1 = min(cx + r, G - 1);
        for (int z = z0; z <= z1; z++) {
            float dz = slabdist(qz, z);
            float dz2 = dz * dz;
            for (int y = y0; y <= y1; y++) {
                float dy = slabdist(qy, y);
                if (fmaf(dy, dy, dz2) >= best) continue;
                int rb = (z * G + y) * G + tb;
                scan_range(g_start[rb + x0], g_start[rb + x1 + 1], qx, qy, qz, best);
            }
        }
    }
    g_minv[__float_as_int(q.w)] = best;   // write by ORIGINAL index: deterministic
}

// ---------------- 6. single-kernel deterministic reduction ----------------
__global__ void __launch_bounds__(1024) k_reduce(float* __restrict__ out) {
    __shared__ float sm[1024];
    int t = threadIdx.x;
    float acc = 0.0f;
    const float4* mv = (const float4*)g_minv;
#pragma unroll
    for (int k = 0; k < NALL / 4096; k++) {          // 16 x float4 per thread
        float4 v = mv[t + k * 1024];
        acc += (v.x + v.y) + (v.z + v.w);
    }
    sm[t] = acc; __syncthreads();
    for (int stride = 512; stride > 0; stride >>= 1) {
        if (t < stride) sm[t] += sm[t + stride];
        __syncthreads();
    }
    if (t == 0) out[0] = sm[0] / (float)NPTS;
}

extern "C" void kernel_launch(void* const* d_in, const int* in_sizes, int n_in,
                              void* d_out, int out_size) {
    const float* pred   = (const float*)d_in[0];
    const float* target = (const float*)d_in[1];
    float* out = (float*)d_out;

    k_hist      <<<NALL / 256, 256>>>(pred, target);
    k_scan1     <<<NC2 / 1024, 256>>>();
    k_scan2apply<<<NC2 / 1024, 256>>>();
    k_scatter   <<<NALL / 256, 256>>>(pred, target);
    k_query     <<<NALL / 256, 256>>>();
    k_reduce    <<<1, 1024>>>(out);
}

// round 15
// speedup vs baseline: 1.2262x; 1.0190x over previous
#include <cuda_runtime.h>
#include <cuda_bf16.h>

// ChamferLoss via exact uniform-grid nearest neighbor (G=32).
// pred[32768,3], target[32768,3] float32, out = mean NN^2 both directions.
//
// 1. histogram  2. scan stage1 (per-tile, self-zeroes counts for next replay)
// 3. scan stage2 (per-block prefix of tile sums, writes CSR starts)
// 4. scatter (cell-sorted, carries original index)
// 5. query: r=1 box with ALL 18 CSR boundaries prefetched up-front (MLP),
//    center-row-first + slab-distance row pruning, exact termination
// 6. single-kernel deterministic reduction (float4 loads).

#define NPTS   32768
#define NALL   65536
#define G      32
#define NC     (G*G*G)       // 32768 cells per set
#define NC2    (2*NC)        // 65536
#define GLO    (-4.0f)
#define GH     (0.25f)       // 8/32, exact
#define GINV   (4.0f)        // 1/GH, exact
#define FINF   3.4e38f

__device__ uint    g_cnt[NC2];       // zero at start of every run (see k_scan1)
__device__ uint    g_scanpart[NC2];
__device__ uint    g_bsum[64];
__device__ uint    g_start[NC2 + 1];
__device__ uint    g_cursor[NC2];
__device__ float4  g_pts[NALL];      // cell-sorted; .w = original global idx bits
__device__ float   g_minv[NALL];     // per-ORIGINAL-index min sq distance

__device__ __forceinline__ int cellof(float v) {
    int c = (int)floorf((v - GLO) * GINV);
    return min(max(c, 0), G - 1);
}
// distance from q to the slab of cell index c along one axis (0 if inside)
__device__ __forceinline__ float slabdist(float q, int c) {
    float l = GLO + c * GH;
    return fmaxf(0.0f, fmaxf(l - q, q - (l + GH)));
}

// ---------------- 1. histogram (g_cnt is zero on entry, every run) --------
__global__ void __launch_bounds__(256) k_hist(const float* __restrict__ pred,
                                              const float* __restrict__ target) {
    int i = blockIdx.x * 256 + threadIdx.x;          // 0..NALL-1
    int s = i >> 15;
    int li = i & (NPTS - 1);
    const float* src = s ? target : pred;
    float x = src[3 * li], y = src[3 * li + 1], z = src[3 * li + 2];
    int c = ((cellof(z) * G + cellof(y)) * G + cellof(x)) + s * NC;
    atomicAdd(&g_cnt[c], 1u);
}

// ------ 2. scan stage 1: per-1024-cell tile; re-zeroes g_cnt after read ----
__global__ void __launch_bounds__(256) k_scan1() {
    __shared__ uint sm[256];
    int t = threadIdx.x;
    int base = blockIdx.x * 1024 + t * 4;
    uint4 c4 = *(const uint4*)&g_cnt[base];
    *(uint4*)&g_cnt[base] = make_uint4(0, 0, 0, 0);   // clean for next replay
    uint s = c4.x + c4.y + c4.z + c4.w;
    sm[t] = s; __syncthreads();
    for (int off = 1; off < 256; off <<= 1) {
        uint v = (t >= off) ? sm[t - off] : 0u;
        __syncthreads();
        sm[t] += v;
        __syncthreads();
    }
    uint excl = sm[t] - s;
    g_scanpart[base]     = excl;
    g_scanpart[base + 1] = excl + c4.x;
    g_scanpart[base + 2] = excl + c4.x + c4.y;
    g_scanpart[base + 3] = excl + c4.x + c4.y + c4.z;
    if (t == 255) g_bsum[blockIdx.x] = sm[255];
}

// ------ 3. scan stage 2: each block derives its own tile prefix, applies ---
__global__ void __launch_bounds__(256) k_scan2apply() {
    __shared__ uint soff;
    int t = threadIdx.x;
    if (t < 32) {
        uint a = (2 * t     < (int)blockIdx.x) ? g_bsum[2 * t]     : 0u;
        uint b = (2 * t + 1 < (int)blockIdx.x) ? g_bsum[2 * t + 1] : 0u;
        uint v = a + b;
#pragma unroll
        for (int o = 16; o > 0; o >>= 1)
            v += __shfl_down_sync(0xFFFFFFFFu, v, o);
        if (t == 0) soff = v;
    }
    __syncthreads();
    uint off = soff;
    int base = blockIdx.x * 1024 + t * 4;
#pragma unroll
    for (int k = 0; k < 4; k++) {
        uint v = g_scanpart[base + k] + off;
        g_start[base + k] = v;
        g_cursor[base + k] = v;
    }
    if (blockIdx.x == 63 && t == 255) g_start[NC2] = NALL;
}

// ---------------- 4. scatter (sorted by cell) ----------------
__global__ void __launch_bounds__(256) k_scatter(const float* __restrict__ pred,
                                                 const float* __restrict__ target) {
    int i = blockIdx.x * 256 + threadIdx.x;          // global original idx
    int s = i >> 15;
    int li = i & (NPTS - 1);
    const float* src = s ? target : pred;
    float x = src[3 * li], y = src[3 * li + 1], z = src[3 * li + 2];
    int c = ((cellof(z) * G + cellof(y)) * G + cellof(x)) + s * NC;
    uint pos = atomicAdd(&g_cursor[c], 1u);
    g_pts[pos] = make_float4(x, y, z, __int_as_float(i));
}

// ---------------- 5. query: pruned expanding-box exact NN ----------------
__device__ __forceinline__ void scan_range(uint k0, uint k1,
                                           float qx, float qy, float qz,
                                           float& best) {
    for (uint k = k0; k < k1; k++) {
        float4 p = g_pts[k];
        float dx = p.x - qx, dy = p.y - qy, dz = p.z - qz;
        best = fminf(best, fmaf(dx, dx, fmaf(dy, dy, dz * dz)));
    }
}

__global__ void __launch_bounds__(256) k_query() {
    int i = blockIdx.x * 256 + threadIdx.x;          // sorted position
    float4 q = g_pts[i];
    int s = i >> 15;                                 // set of this query
    int tb = (s ^ 1) * NC;                           // target grid base
    float qx = q.x, qy = q.y, qz = q.z;
    int cx = cellof(qx), cy = cellof(qy), cz = cellof(qz);

    // distance of the query outside its (clamped) cell: keeps bound exact
    float ex = fmaxf(slabdist(qx, cx), fmaxf(slabdist(qy, cy), slabdist(qz, cz)));

    float best = FINF;

    // ---- r = 1: prefetch ALL 9 rows' CSR boundaries first (18 independent
    //      loads in flight), then scan center row, then pruned rows ----
    {
        int x0 = max(cx - 1, 0), x1 = min(cx + 1, G - 1);
        uint s0[9], s1[9];
#pragma unroll
        for (int dz = -1; dz <= 1; dz++) {
#pragma unroll
            for (int dy = -1; dy <= 1; dy++) {
                int idx = (dz + 1) * 3 + (dy + 1);
                int z = cz + dz, y = cy + dy;
                bool ok = (z >= 0) && (z < G) && (y >= 0) && (y < G);
                int zc = min(max(z, 0), G - 1), yc = min(max(y, 0), G - 1);
                int rb = (zc * G + yc) * G + tb;
                // clamped address is always valid; empty range when row OOB
                uint a = g_start[rb + x0];
                uint b = g_start[rb + x1 + 1];
                s0[idx] = ok ? a : 0u;
                s1[idx] = ok ? b : 0u;
            }
        }
        // center row first: tight pruning bound
        scan_range(s0[4], s1[4], qx, qy, qz, best);
#pragma unroll
        for (int dz = -1; dz <= 1; dz++) {
            float dzs = slabdist(qz, cz + dz);
            float dz2 = dzs * dzs;
#pragma unroll
            for (int dy = -1; dy <= 1; dy++) {
                if (dz == 0 && dy == 0) continue;
                int idx = (dz + 1) * 3 + (dy + 1);
                float dys = slabdist(qy, cy + dy);
                if (fmaf(dys, dys, dz2) >= best) continue;   // row cannot improve
                scan_range(s0[idx], s1[idx], qx, qy, qz, best);
            }
        }
    }

    // ---- escalation: full pruned box per radius, exact termination ----
    int r = 1;
    for (;;) {
        float bnd = (float)r * GH - ex;   // unexamined cells are farther than this
        if ((bnd > 0.0f && best <= bnd * bnd) || r >= G) break;
        r++;
        int z0 = max(cz - r, 0), z1 = min(cz + r, G - 1);
        int y0 = max(cy - r, 0), y1 = min(cy + r, G - 1);
        int x0 = max(cx - r, 0), x1 = min(cx + r, G - 1);
        for (int z = z0; z <= z1; z++) {
            float dz = slabdist(qz, z);
            float dz2 = dz * dz;
            for (int y = y0; y <= y1; y++) {
                float dy = slabdist(qy, y);
                if (fmaf(dy, dy, dz2) >= best) continue;
                int rb = (z * G + y) * G + tb;
                scan_range(g_start[rb + x0], g_start[rb + x1 + 1], qx, qy, qz, best);
            }
        }
    }
    g_minv[__float_as_int(q.w)] = best;   // write by ORIGINAL index: deterministic
}

// ---------------- 6. single-kernel deterministic reduction ----------------
__global__ void __launch_bounds__(1024) k_reduce(float* __restrict__ out) {
    __shared__ float sm[1024];
    int t = threadIdx.x;
    float acc = 0.0f;
    const float4* mv = (const float4*)g_minv;
#pragma unroll
    for (int k = 0; k < NALL / 4096; k++) {          // 16 x float4 per thread
        float4 v = mv[t + k * 1024];
        acc += (v.x + v.y) + (v.z + v.w);
    }
    sm[t] = acc; __syncthreads();
    for (int stride = 512; stride > 0; stride >>= 1) {
        if (t < stride) sm[t] += sm[t + stride];
        __syncthreads();
    }
    if (t == 0) out[0] = sm[0] / (float)NPTS;
}

extern "C" void kernel_launch(void* const* d_in, const int* in_sizes, int n_in,
                              void* d_out, int out_size) {
    const float* pred   = (const float*)d_in[0];
    const float* target = (const float*)d_in[1];
    float* out = (float*)d_out;

    k_hist      <<<NALL / 256, 256>>>(pred, target);
    k_scan1     <<<NC2 / 1024, 256>>>();
    k_scan2apply<<<NC2 / 1024, 256>>>();
    k_scatter   <<<NALL / 256, 256>>>(pred, target);
    k_query     <<<NALL / 256, 256>>>();
    k_reduce    <<<1, 1024>>>(out);
}